// round 2
// baseline (speedup 1.0000x reference)
#include <cuda_runtime.h>
#include <cstdint>

#define E_EXPERTS 8
#define T_TOKENS  4096
#define D_MODEL   1024
#define F_FF      4096
#define TOPK      2
#define GROUPSZ   128

// ---------------- scratch (__device__ globals; no allocation) ----------------
__device__ int   g_cnt[E_EXPERTS];
__device__ int   g_off[E_EXPERTS + 1];
__device__ int   g_tok[T_TOKENS * TOPK];        // slot -> token
__device__ int   g_tok_eid[T_TOKENS * TOPK];    // token*2+k -> expert id
__device__ int   g_tok_slot[T_TOKENS * TOPK];   // token*2+k -> slot
__device__ float g_tok_coef[T_TOKENS * TOPK];   // token*2+k -> coef
__device__ float g_act[(size_t)T_TOKENS * TOPK * F_FF];    // 128 MB
__device__ float g_y[(size_t)T_TOKENS * TOPK * D_MODEL];   // 32 MB

// ---------------- helpers ----------------
__device__ __forceinline__ float to_tf32(float v) {
    uint32_t r;
    asm("cvt.rna.tf32.f32 %0, %1;" : "=r"(r) : "f"(v));
    return __uint_as_float(r);
}

#define MMA_TF32(c, a, b)                                                      \
    asm volatile(                                                              \
        "mma.sync.aligned.m16n8k8.row.col.f32.tf32.tf32.f32 "                  \
        "{%0,%1,%2,%3}, {%4,%5,%6,%7}, {%8,%9}, {%0,%1,%2,%3};\n"              \
        : "+f"((c)[0]), "+f"((c)[1]), "+f"((c)[2]), "+f"((c)[3])               \
        : "r"((a)[0]), "r"((a)[1]), "r"((a)[2]), "r"((a)[3]),                  \
          "r"((b)[0]), "r"((b)[1]))

// ---------------- routing ----------------
__global__ void k_zero_counts() {
    if (threadIdx.x < E_EXPERTS) g_cnt[threadIdx.x] = 0;
}

__global__ void k_route(const float* __restrict__ gating) {
    int t = blockIdx.x * blockDim.x + threadIdx.x;
    if (t >= T_TOKENS) return;
    float l[E_EXPERTS];
#pragma unroll
    for (int i = 0; i < E_EXPERTS; i++) l[i] = gating[t * E_EXPERTS + i];
    int ia = -1, ib = -1;
    float va = -1e30f, vb = -1e30f;
#pragma unroll
    for (int i = 0; i < E_EXPERTS; i++) {
        float v = l[i];
        if (v > va) { vb = va; ib = ia; va = v; ia = i; }
        else if (v > vb) { vb = v; ib = i; }
    }
    // renormalized top-2 softmax weights: full softmax denominator cancels
    float eb = expf(vb - va);
    float inv = 1.0f / (1.0f + eb);
    g_tok_eid[2 * t + 0] = ia;
    g_tok_eid[2 * t + 1] = ib;
    g_tok_coef[2 * t + 0] = inv;
    g_tok_coef[2 * t + 1] = eb * inv;
    atomicAdd(&g_cnt[ia], 1);
    atomicAdd(&g_cnt[ib], 1);
}

// deterministic compaction: warp w handles expert w, token order ascending
__global__ void k_place() {
    int lane = threadIdx.x & 31;
    int e = threadIdx.x >> 5;
    if (e >= E_EXPERTS) return;
    int off = 0;
    for (int i = 0; i < e; i++) off += g_cnt[i];
    if (lane == 0) {
        g_off[e] = off;
        if (e == E_EXPERTS - 1) g_off[E_EXPERTS] = off + g_cnt[e];
    }
    int cursor = off;
    for (int base = 0; base < T_TOKENS; base += 32) {
        int t = base + lane;
        int e0 = g_tok_eid[2 * t], e1 = g_tok_eid[2 * t + 1];
        bool m0 = (e0 == e), m1 = (e1 == e);
        bool m = m0 || m1;
        unsigned mask = __ballot_sync(0xffffffffu, m);
        if (m) {
            int pos = cursor + __popc(mask & ((1u << lane) - 1u));
            g_tok[pos] = t;
            g_tok_slot[2 * t + (m0 ? 0 : 1)] = pos;
        }
        cursor += __popc(mask);
    }
}

// ---------------- GEMM1: act = silu(x@Wgate) * (x@Wup), tf32 mma ----------------
// Tile: BM=128 rows x (BN=64 gate + BN=64 up), BK=32. 256 threads (8 warps, 2x4).
__global__ __launch_bounds__(256, 2) void k_gemm1(
    const float* __restrict__ x,
    const int* __restrict__ w1q,
    const float* __restrict__ w1s)
{
    int e = blockIdx.z;
    int cnt = g_cnt[e];
    int row0 = blockIdx.y * 128;
    if (row0 >= cnt) return;
    int rows = cnt - row0; if (rows > 128) rows = 128;
    int base = g_off[e];
    int n0 = blockIdx.x * 64;

    __shared__ float As[128][36];
    __shared__ float Bg[32][68];
    __shared__ float Bu[32][68];
    __shared__ int toks[128];

    int tid = threadIdx.x;
    if (tid < 128) {
        int rr = tid < rows ? tid : rows - 1;
        toks[tid] = g_tok[base + row0 + rr];
    }
    __syncthreads();

    int lane = tid & 31, wid = tid >> 5;
    int wm = wid >> 2, wn = wid & 3;        // warp tile: 64(m) x 16(n) per strip
    int gid = lane >> 2, tig = lane & 3;

    float accG[4][2][4], accU[4][2][4];
#pragma unroll
    for (int i = 0; i < 4; i++)
#pragma unroll
        for (int j = 0; j < 2; j++)
#pragma unroll
            for (int r = 0; r < 4; r++) { accG[i][j][r] = 0.f; accU[i][j][r] = 0.f; }

    const int* wrow_base = w1q + (size_t)e * D_MODEL * (2 * F_FF);
    const float* srow_base = w1s + (size_t)e * (D_MODEL / GROUPSZ) * (2 * F_FF);

    int arow = tid >> 3, ac4 = tid & 7;     // A: 128x32 f32 as float4
    int brow = tid >> 4, bc4 = tid & 15;    // B: 32x64 int as int4

    for (int k0 = 0; k0 < D_MODEL; k0 += 32) {
#pragma unroll
        for (int r = 0; r < 4; r++) {
            int rr = arow + r * 32;
            float4 v = *reinterpret_cast<const float4*>(
                x + (size_t)toks[rr] * D_MODEL + k0 + ac4 * 4);
            v.x = to_tf32(v.x); v.y = to_tf32(v.y);
            v.z = to_tf32(v.z); v.w = to_tf32(v.w);
            *reinterpret_cast<float4*>(&As[rr][ac4 * 4]) = v;
        }
        int grp = k0 >> 7;  // BK=32 aligned => one scale group per k-tile
        const float* sg = srow_base + (size_t)grp * (2 * F_FF) + n0;
        const float* su = sg + F_FF;
#pragma unroll
        for (int r = 0; r < 2; r++) {
            int kk = brow + r * 16;
            const int* wr = wrow_base + (size_t)(k0 + kk) * (2 * F_FF) + n0;
            int4 q = *reinterpret_cast<const int4*>(wr + bc4 * 4);
            Bg[kk][bc4 * 4 + 0] = to_tf32((float)(q.x - 8) * __ldg(sg + bc4 * 4 + 0));
            Bg[kk][bc4 * 4 + 1] = to_tf32((float)(q.y - 8) * __ldg(sg + bc4 * 4 + 1));
            Bg[kk][bc4 * 4 + 2] = to_tf32((float)(q.z - 8) * __ldg(sg + bc4 * 4 + 2));
            Bg[kk][bc4 * 4 + 3] = to_tf32((float)(q.w - 8) * __ldg(sg + bc4 * 4 + 3));
            int4 q2 = *reinterpret_cast<const int4*>(wr + F_FF + bc4 * 4);
            Bu[kk][bc4 * 4 + 0] = to_tf32((float)(q2.x - 8) * __ldg(su + bc4 * 4 + 0));
            Bu[kk][bc4 * 4 + 1] = to_tf32((float)(q2.y - 8) * __ldg(su + bc4 * 4 + 1));
            Bu[kk][bc4 * 4 + 2] = to_tf32((float)(q2.z - 8) * __ldg(su + bc4 * 4 + 2));
            Bu[kk][bc4 * 4 + 3] = to_tf32((float)(q2.w - 8) * __ldg(su + bc4 * 4 + 3));
        }
        __syncthreads();
#pragma unroll
        for (int ks = 0; ks < 4; ks++) {
            uint32_t a[4][4];
#pragma unroll
            for (int mf = 0; mf < 4; mf++) {
                int m = wm * 64 + mf * 16;
                a[mf][0] = __float_as_uint(As[m + gid][ks * 8 + tig]);
                a[mf][1] = __float_as_uint(As[m + gid + 8][ks * 8 + tig]);
                a[mf][2] = __float_as_uint(As[m + gid][ks * 8 + tig + 4]);
                a[mf][3] = __float_as_uint(As[m + gid + 8][ks * 8 + tig + 4]);
            }
            uint32_t bg[2][2], bu[2][2];
#pragma unroll
            for (int nf = 0; nf < 2; nf++) {
                int n = wn * 16 + nf * 8 + gid;
                bg[nf][0] = __float_as_uint(Bg[ks * 8 + tig][n]);
                bg[nf][1] = __float_as_uint(Bg[ks * 8 + tig + 4][n]);
                bu[nf][0] = __float_as_uint(Bu[ks * 8 + tig][n]);
                bu[nf][1] = __float_as_uint(Bu[ks * 8 + tig + 4][n]);
            }
#pragma unroll
            for (int mf = 0; mf < 4; mf++)
#pragma unroll
                for (int nf = 0; nf < 2; nf++) {
                    MMA_TF32(accG[mf][nf], a[mf], bg[nf]);
                    MMA_TF32(accU[mf][nf], a[mf], bu[nf]);
                }
        }
        __syncthreads();
    }
    // epilogue: silu(gate)*up -> g_act
#pragma unroll
    for (int mf = 0; mf < 4; mf++) {
#pragma unroll
        for (int half = 0; half < 2; half++) {
            int ml = wm * 64 + mf * 16 + gid + half * 8;
            if (ml < rows) {
                size_t slot = (size_t)(base + row0 + ml);
#pragma unroll
                for (int nf = 0; nf < 2; nf++) {
                    int j = n0 + wn * 16 + nf * 8 + tig * 2;
                    float gv0 = accG[mf][nf][half * 2 + 0];
                    float gv1 = accG[mf][nf][half * 2 + 1];
                    float uv0 = accU[mf][nf][half * 2 + 0];
                    float uv1 = accU[mf][nf][half * 2 + 1];
                    float v0 = gv0 / (1.0f + __expf(-gv0)) * uv0;
                    float v1 = gv1 / (1.0f + __expf(-gv1)) * uv1;
                    *reinterpret_cast<float2*>(&g_act[slot * F_FF + j]) =
                        make_float2(v0, v1);
                }
            }
        }
    }
}

// ---------------- GEMM2: y[slot] = act @ dequant(w2), tf32 mma ----------------
// Tile: BM=128 x BN=128, BK=32. 256 threads (8 warps, 2x4), warp tile 64x32.
__global__ __launch_bounds__(256, 2) void k_gemm2(
    const int* __restrict__ w2q,
    const float* __restrict__ w2s)
{
    int e = blockIdx.z;
    int cnt = g_cnt[e];
    int row0 = blockIdx.y * 128;
    if (row0 >= cnt) return;
    int rows = cnt - row0; if (rows > 128) rows = 128;
    int base = g_off[e];
    int n0 = blockIdx.x * 128;

    __shared__ float As[128][36];
    __shared__ float Bs[32][132];

    int tid = threadIdx.x;
    int lane = tid & 31, wid = tid >> 5;
    int wm = wid >> 2, wn = wid & 3;        // warp tile 64(m) x 32(n)
    int gid = lane >> 2, tig = lane & 3;

    float acc[4][4][4];
#pragma unroll
    for (int i = 0; i < 4; i++)
#pragma unroll
        for (int j = 0; j < 4; j++)
#pragma unroll
            for (int r = 0; r < 4; r++) acc[i][j][r] = 0.f;

    const int* wrow_base = w2q + (size_t)e * F_FF * D_MODEL;
    const float* srow_base = w2s + (size_t)e * (F_FF / GROUPSZ) * D_MODEL;

    int arow = tid >> 3, ac4 = tid & 7;
    int brow = tid >> 5, bc4 = tid & 31;

    for (int k0 = 0; k0 < F_FF; k0 += 32) {
#pragma unroll
        for (int r = 0; r < 4; r++) {
            int rr = arow + r * 32;
            int rv = rr < rows ? rr : rows - 1;
            float4 v = *reinterpret_cast<const float4*>(
                g_act + (size_t)(base + row0 + rv) * F_FF + k0 + ac4 * 4);
            v.x = to_tf32(v.x); v.y = to_tf32(v.y);
            v.z = to_tf32(v.z); v.w = to_tf32(v.w);
            *reinterpret_cast<float4*>(&As[rr][ac4 * 4]) = v;
        }
        int grp = k0 >> 7;
        const float* sr = srow_base + (size_t)grp * D_MODEL + n0;
#pragma unroll
        for (int r = 0; r < 4; r++) {
            int kk = brow + r * 8;
            const int* wr = wrow_base + (size_t)(k0 + kk) * D_MODEL + n0;
            int4 q = *reinterpret_cast<const int4*>(wr + bc4 * 4);
            Bs[kk][bc4 * 4 + 0] = to_tf32((float)(q.x - 8) * __ldg(sr + bc4 * 4 + 0));
            Bs[kk][bc4 * 4 + 1] = to_tf32((float)(q.y - 8) * __ldg(sr + bc4 * 4 + 1));
            Bs[kk][bc4 * 4 + 2] = to_tf32((float)(q.z - 8) * __ldg(sr + bc4 * 4 + 2));
            Bs[kk][bc4 * 4 + 3] = to_tf32((float)(q.w - 8) * __ldg(sr + bc4 * 4 + 3));
        }
        __syncthreads();
#pragma unroll
        for (int ks = 0; ks < 4; ks++) {
            uint32_t a[4][4];
#pragma unroll
            for (int mf = 0; mf < 4; mf++) {
                int m = wm * 64 + mf * 16;
                a[mf][0] = __float_as_uint(As[m + gid][ks * 8 + tig]);
                a[mf][1] = __float_as_uint(As[m + gid + 8][ks * 8 + tig]);
                a[mf][2] = __float_as_uint(As[m + gid][ks * 8 + tig + 4]);
                a[mf][3] = __float_as_uint(As[m + gid + 8][ks * 8 + tig + 4]);
            }
            uint32_t b[4][2];
#pragma unroll
            for (int nf = 0; nf < 4; nf++) {
                int n = wn * 32 + nf * 8 + gid;
                b[nf][0] = __float_as_uint(Bs[ks * 8 + tig][n]);
                b[nf][1] = __float_as_uint(Bs[ks * 8 + tig + 4][n]);
            }
#pragma unroll
            for (int mf = 0; mf < 4; mf++)
#pragma unroll
                for (int nf = 0; nf < 4; nf++)
                    MMA_TF32(acc[mf][nf], a[mf], b[nf]);
        }
        __syncthreads();
    }
#pragma unroll
    for (int mf = 0; mf < 4; mf++) {
#pragma unroll
        for (int half = 0; half < 2; half++) {
            int ml = wm * 64 + mf * 16 + gid + half * 8;
            if (ml < rows) {
                size_t slot = (size_t)(base + row0 + ml);
#pragma unroll
                for (int nf = 0; nf < 4; nf++) {
                    int j = n0 + wn * 32 + nf * 8 + tig * 2;
                    *reinterpret_cast<float2*>(&g_y[slot * D_MODEL + j]) =
                        make_float2(acc[mf][nf][half * 2 + 0],
                                    acc[mf][nf][half * 2 + 1]);
                }
            }
        }
    }
}

// ---------------- combine: out[t] = c0*y[s0] + c1*y[s1] ----------------
__global__ void k_combine(float* __restrict__ out) {
    int t = blockIdx.x;
    int d = threadIdx.x * 4;
    int s0 = g_tok_slot[2 * t], s1 = g_tok_slot[2 * t + 1];
    float c0 = g_tok_coef[2 * t], c1 = g_tok_coef[2 * t + 1];
    float4 y0 = *reinterpret_cast<const float4*>(&g_y[(size_t)s0 * D_MODEL + d]);
    float4 y1 = *reinterpret_cast<const float4*>(&g_y[(size_t)s1 * D_MODEL + d]);
    float4 o;
    o.x = c0 * y0.x + c1 * y1.x;
    o.y = c0 * y0.y + c1 * y1.y;
    o.z = c0 * y0.z + c1 * y1.z;
    o.w = c0 * y0.w + c1 * y1.w;
    *reinterpret_cast<float4*>(out + (size_t)t * D_MODEL + d) = o;
}

// ---------------- launch ----------------
extern "C" void kernel_launch(void* const* d_in, const int* in_sizes, int n_in,
                              void* d_out, int out_size) {
    const float* x      = (const float*)d_in[0];
    const float* gating = (const float*)d_in[1];
    const int*   w1q    = (const int*)d_in[2];
    const int*   w2q    = (const int*)d_in[3];
    const float* w1s    = (const float*)d_in[4];
    const float* w2s    = (const float*)d_in[5];
    float* out = (float*)d_out;
    (void)in_sizes; (void)n_in; (void)out_size;

    k_zero_counts<<<1, 32>>>();
    k_route<<<T_TOKENS / 256, 256>>>(gating);
    k_place<<<1, 256>>>();

    dim3 g1(F_FF / 64, T_TOKENS / 128, E_EXPERTS);   // 64 x 32 x 8, early-exit on m
    k_gemm1<<<g1, 256>>>(x, w1q, w1s);

    dim3 g2(D_MODEL / 128, T_TOKENS / 128, E_EXPERTS);  // 8 x 32 x 8
    k_gemm2<<<g2, 256>>>(w2q, w2s);

    k_combine<<<T_TOKENS, 256>>>(out);
}

// round 4
// speedup vs baseline: 1.2760x; 1.2760x over previous
#include <cuda_runtime.h>
#include <cstdint>

#define E_EXPERTS 8
#define T_TOKENS  4096
#define D_MODEL   1024
#define F_FF      4096
#define TOPK      2
#define GROUPSZ   128

// ---------------- scratch (__device__ globals; no allocation) ----------------
__device__ int   g_cnt[E_EXPERTS];
__device__ int   g_off[E_EXPERTS + 1];
__device__ int   g_tok[T_TOKENS * TOPK];        // slot -> token
__device__ int   g_tok_eid[T_TOKENS * TOPK];    // token*2+k -> expert id
__device__ int   g_tok_slot[T_TOKENS * TOPK];   // token*2+k -> slot
__device__ float g_tok_coef[T_TOKENS * TOPK];   // token*2+k -> coef
__device__ float g_act[(size_t)T_TOKENS * TOPK * F_FF];    // 128 MB
__device__ float g_y[(size_t)T_TOKENS * TOPK * D_MODEL];   // 32 MB

// ---------------- helpers ----------------
__device__ __forceinline__ float to_tf32(float v) {
    uint32_t r;
    asm("cvt.rna.tf32.f32 %0, %1;" : "=r"(r) : "f"(v));
    return __uint_as_float(r);
}

#define MMA_TF32(c, a, b)                                                      \
    asm volatile(                                                              \
        "mma.sync.aligned.m16n8k8.row.col.f32.tf32.tf32.f32 "                  \
        "{%0,%1,%2,%3}, {%4,%5,%6,%7}, {%8,%9}, {%0,%1,%2,%3};\n"              \
        : "+f"((c)[0]), "+f"((c)[1]), "+f"((c)[2]), "+f"((c)[3])               \
        : "r"((a)[0]), "r"((a)[1]), "r"((a)[2]), "r"((a)[3]),                  \
          "r"((b)[0]), "r"((b)[1]))

// ---------------- routing ----------------
__global__ void k_zero_counts() {
    if (threadIdx.x < E_EXPERTS) g_cnt[threadIdx.x] = 0;
}

__global__ void k_route(const float* __restrict__ gating) {
    int t = blockIdx.x * blockDim.x + threadIdx.x;
    if (t >= T_TOKENS) return;
    float l[E_EXPERTS];
#pragma unroll
    for (int i = 0; i < E_EXPERTS; i++) l[i] = gating[t * E_EXPERTS + i];
    int ia = -1, ib = -1;
    float va = -1e30f, vb = -1e30f;
#pragma unroll
    for (int i = 0; i < E_EXPERTS; i++) {
        float v = l[i];
        if (v > va) { vb = va; ib = ia; va = v; ia = i; }
        else if (v > vb) { vb = v; ib = i; }
    }
    float eb = expf(vb - va);
    float inv = 1.0f / (1.0f + eb);
    g_tok_eid[2 * t + 0] = ia;
    g_tok_eid[2 * t + 1] = ib;
    g_tok_coef[2 * t + 0] = inv;
    g_tok_coef[2 * t + 1] = eb * inv;
    atomicAdd(&g_cnt[ia], 1);
    atomicAdd(&g_cnt[ib], 1);
}

// deterministic compaction: warp w handles expert w, token order ascending
__global__ void k_place() {
    int lane = threadIdx.x & 31;
    int e = threadIdx.x >> 5;
    if (e >= E_EXPERTS) return;
    int off = 0;
    for (int i = 0; i < e; i++) off += g_cnt[i];
    if (lane == 0) {
        g_off[e] = off;
        if (e == E_EXPERTS - 1) g_off[E_EXPERTS] = off + g_cnt[e];
    }
    int cursor = off;
    for (int base = 0; base < T_TOKENS; base += 32) {
        int t = base + lane;
        int e0 = g_tok_eid[2 * t], e1 = g_tok_eid[2 * t + 1];
        bool m0 = (e0 == e), m1 = (e1 == e);
        bool m = m0 || m1;
        unsigned mask = __ballot_sync(0xffffffffu, m);
        if (m) {
            int pos = cursor + __popc(mask & ((1u << lane) - 1u));
            g_tok[pos] = t;
            g_tok_slot[2 * t + (m0 ? 0 : 1)] = pos;
        }
        cursor += __popc(mask);
    }
}

// ---------------- GEMM1: act = silu(x@Wgate) * (x@Wup), tf32 mma ----------------
// Tile: BM=128 rows x (BN=64 gate + BN=64 up), BK=32. 256 threads (8 warps, 2x4).
// Software-pipelined: next k-tile LDG'd into registers during current mma phase.
__global__ __launch_bounds__(256, 2) void k_gemm1(
    const float* __restrict__ x,
    const int* __restrict__ w1q,
    const float* __restrict__ w1s)
{
    int e = blockIdx.z;
    int cnt = g_cnt[e];
    int row0 = blockIdx.y * 128;
    if (row0 >= cnt) return;
    int rows = cnt - row0; if (rows > 128) rows = 128;
    int base = g_off[e];
    int n0 = blockIdx.x * 64;

    __shared__ float As[128][36];
    __shared__ float Bg[32][68];
    __shared__ float Bu[32][68];
    __shared__ int toks[128];

    int tid = threadIdx.x;
    if (tid < 128) {
        int rr = tid < rows ? tid : rows - 1;
        toks[tid] = g_tok[base + row0 + rr];
    }
    __syncthreads();

    int lane = tid & 31, wid = tid >> 5;
    int wm = wid >> 2, wn = wid & 3;        // warp tile: 64(m) x 16(n) per strip
    int gid = lane >> 2, tig = lane & 3;

    float accG[4][2][4], accU[4][2][4];
#pragma unroll
    for (int i = 0; i < 4; i++)
#pragma unroll
        for (int j = 0; j < 2; j++)
#pragma unroll
            for (int r = 0; r < 4; r++) { accG[i][j][r] = 0.f; accU[i][j][r] = 0.f; }

    const int* wrow_base = w1q + (size_t)e * D_MODEL * (2 * F_FF);
    const float* srow_base = w1s + (size_t)e * (D_MODEL / GROUPSZ) * (2 * F_FF);

    int arow = tid >> 3, ac4 = tid & 7;     // A: 128x32 f32 as float4
    int brow = tid >> 4, bc4 = tid & 15;    // B: 32x64 int as int4

    // register staging for the software pipeline
    float4 aReg[4];
    int4   bgReg[2], buReg[2];

    // prologue: fetch tile 0
#pragma unroll
    for (int r = 0; r < 4; r++) {
        int rr = arow + r * 32;
        aReg[r] = *reinterpret_cast<const float4*>(
            x + (size_t)toks[rr] * D_MODEL + 0 + ac4 * 4);
    }
#pragma unroll
    for (int r = 0; r < 2; r++) {
        int kk = brow + r * 16;
        const int* wr = wrow_base + (size_t)kk * (2 * F_FF) + n0;
        bgReg[r] = *reinterpret_cast<const int4*>(wr + bc4 * 4);
        buReg[r] = *reinterpret_cast<const int4*>(wr + F_FF + bc4 * 4);
    }

    for (int k0 = 0; k0 < D_MODEL; k0 += 32) {
        // ---- STS phase: dequant + store staged tile ----
        int grp = k0 >> 7;
        const float* sg = srow_base + (size_t)grp * (2 * F_FF) + n0 + bc4 * 4;
        float4 s_g = *reinterpret_cast<const float4*>(sg);
        float4 s_u = *reinterpret_cast<const float4*>(sg + F_FF);
#pragma unroll
        for (int r = 0; r < 4; r++) {
            int rr = arow + r * 32;
            float4 v = aReg[r];
            v.x = to_tf32(v.x); v.y = to_tf32(v.y);
            v.z = to_tf32(v.z); v.w = to_tf32(v.w);
            *reinterpret_cast<float4*>(&As[rr][ac4 * 4]) = v;
        }
#pragma unroll
        for (int r = 0; r < 2; r++) {
            int kk = brow + r * 16;
            int4 q = bgReg[r];
            Bg[kk][bc4 * 4 + 0] = to_tf32((float)(q.x - 8) * s_g.x);
            Bg[kk][bc4 * 4 + 1] = to_tf32((float)(q.y - 8) * s_g.y);
            Bg[kk][bc4 * 4 + 2] = to_tf32((float)(q.z - 8) * s_g.z);
            Bg[kk][bc4 * 4 + 3] = to_tf32((float)(q.w - 8) * s_g.w);
            int4 q2 = buReg[r];
            Bu[kk][bc4 * 4 + 0] = to_tf32((float)(q2.x - 8) * s_u.x);
            Bu[kk][bc4 * 4 + 1] = to_tf32((float)(q2.y - 8) * s_u.y);
            Bu[kk][bc4 * 4 + 2] = to_tf32((float)(q2.z - 8) * s_u.z);
            Bu[kk][bc4 * 4 + 3] = to_tf32((float)(q2.w - 8) * s_u.w);
        }
        __syncthreads();

        // ---- prefetch next tile (latency overlapped with mma below) ----
        int k1 = k0 + 32;
        if (k1 < D_MODEL) {
#pragma unroll
            for (int r = 0; r < 4; r++) {
                int rr = arow + r * 32;
                aReg[r] = *reinterpret_cast<const float4*>(
                    x + (size_t)toks[rr] * D_MODEL + k1 + ac4 * 4);
            }
#pragma unroll
            for (int r = 0; r < 2; r++) {
                int kk = brow + r * 16;
                const int* wr = wrow_base + (size_t)(k1 + kk) * (2 * F_FF) + n0;
                bgReg[r] = *reinterpret_cast<const int4*>(wr + bc4 * 4);
                buReg[r] = *reinterpret_cast<const int4*>(wr + F_FF + bc4 * 4);
            }
        }

        // ---- mma phase ----
#pragma unroll
        for (int ks = 0; ks < 4; ks++) {
            uint32_t bg[2][2], bu[2][2];
#pragma unroll
            for (int nf = 0; nf < 2; nf++) {
                int n = wn * 16 + nf * 8 + gid;
                bg[nf][0] = __float_as_uint(Bg[ks * 8 + tig][n]);
                bg[nf][1] = __float_as_uint(Bg[ks * 8 + tig + 4][n]);
                bu[nf][0] = __float_as_uint(Bu[ks * 8 + tig][n]);
                bu[nf][1] = __float_as_uint(Bu[ks * 8 + tig + 4][n]);
            }
#pragma unroll
            for (int mf = 0; mf < 4; mf++) {
                int m = wm * 64 + mf * 16;
                uint32_t a[4];
                a[0] = __float_as_uint(As[m + gid][ks * 8 + tig]);
                a[1] = __float_as_uint(As[m + gid + 8][ks * 8 + tig]);
                a[2] = __float_as_uint(As[m + gid][ks * 8 + tig + 4]);
                a[3] = __float_as_uint(As[m + gid + 8][ks * 8 + tig + 4]);
#pragma unroll
                for (int nf = 0; nf < 2; nf++) {
                    MMA_TF32(accG[mf][nf], a, bg[nf]);
                    MMA_TF32(accU[mf][nf], a, bu[nf]);
                }
            }
        }
        __syncthreads();
    }
    // epilogue: silu(gate)*up -> g_act
#pragma unroll
    for (int mf = 0; mf < 4; mf++) {
#pragma unroll
        for (int half = 0; half < 2; half++) {
            int ml = wm * 64 + mf * 16 + gid + half * 8;
            if (ml < rows) {
                size_t slot = (size_t)(base + row0 + ml);
#pragma unroll
                for (int nf = 0; nf < 2; nf++) {
                    int j = n0 + wn * 16 + nf * 8 + tig * 2;
                    float gv0 = accG[mf][nf][half * 2 + 0];
                    float gv1 = accG[mf][nf][half * 2 + 1];
                    float uv0 = accU[mf][nf][half * 2 + 0];
                    float uv1 = accU[mf][nf][half * 2 + 1];
                    float v0 = gv0 / (1.0f + __expf(-gv0)) * uv0;
                    float v1 = gv1 / (1.0f + __expf(-gv1)) * uv1;
                    *reinterpret_cast<float2*>(&g_act[slot * F_FF + j]) =
                        make_float2(v0, v1);
                }
            }
        }
    }
}

// ---------------- GEMM2: y[slot] = act @ dequant(w2), tf32 mma ----------------
// Tile: BM=128 x BN=128, BK=32. 256 threads (8 warps, 2x4), warp tile 64x32.
// Software-pipelined like GEMM1.
__global__ __launch_bounds__(256, 2) void k_gemm2(
    const int* __restrict__ w2q,
    const float* __restrict__ w2s)
{
    int e = blockIdx.z;
    int cnt = g_cnt[e];
    int row0 = blockIdx.y * 128;
    if (row0 >= cnt) return;
    int rows = cnt - row0; if (rows > 128) rows = 128;
    int base = g_off[e];
    int n0 = blockIdx.x * 128;

    __shared__ float As[128][36];
    __shared__ float Bs[32][132];

    int tid = threadIdx.x;
    int lane = tid & 31, wid = tid >> 5;
    int wm = wid >> 2, wn = wid & 3;        // warp tile 64(m) x 32(n)
    int gid = lane >> 2, tig = lane & 3;

    float acc[4][4][4];
#pragma unroll
    for (int i = 0; i < 4; i++)
#pragma unroll
        for (int j = 0; j < 4; j++)
#pragma unroll
            for (int r = 0; r < 4; r++) acc[i][j][r] = 0.f;

    const int* wrow_base = w2q + (size_t)e * F_FF * D_MODEL;
    const float* srow_base = w2s + (size_t)e * (F_FF / GROUPSZ) * D_MODEL;

    int arow = tid >> 3, ac4 = tid & 7;
    int brow = tid >> 5, bc4 = tid & 31;

    float4 aReg[4];
    int4   bReg[4];

    // prologue: fetch tile 0
#pragma unroll
    for (int r = 0; r < 4; r++) {
        int rr = arow + r * 32;
        int rv = rr < rows ? rr : rows - 1;
        aReg[r] = *reinterpret_cast<const float4*>(
            g_act + (size_t)(base + row0 + rv) * F_FF + 0 + ac4 * 4);
    }
#pragma unroll
    for (int r = 0; r < 4; r++) {
        int kk = brow + r * 8;
        const int* wr = wrow_base + (size_t)kk * D_MODEL + n0;
        bReg[r] = *reinterpret_cast<const int4*>(wr + bc4 * 4);
    }

    for (int k0 = 0; k0 < F_FF; k0 += 32) {
        // ---- STS phase ----
        int grp = k0 >> 7;
        const float* sr = srow_base + (size_t)grp * D_MODEL + n0 + bc4 * 4;
        float4 s = *reinterpret_cast<const float4*>(sr);
#pragma unroll
        for (int r = 0; r < 4; r++) {
            int rr = arow + r * 32;
            float4 v = aReg[r];
            v.x = to_tf32(v.x); v.y = to_tf32(v.y);
            v.z = to_tf32(v.z); v.w = to_tf32(v.w);
            *reinterpret_cast<float4*>(&As[rr][ac4 * 4]) = v;
        }
#pragma unroll
        for (int r = 0; r < 4; r++) {
            int kk = brow + r * 8;
            int4 q = bReg[r];
            Bs[kk][bc4 * 4 + 0] = to_tf32((float)(q.x - 8) * s.x);
            Bs[kk][bc4 * 4 + 1] = to_tf32((float)(q.y - 8) * s.y);
            Bs[kk][bc4 * 4 + 2] = to_tf32((float)(q.z - 8) * s.z);
            Bs[kk][bc4 * 4 + 3] = to_tf32((float)(q.w - 8) * s.w);
        }
        __syncthreads();

        // ---- prefetch next tile ----
        int k1 = k0 + 32;
        if (k1 < F_FF) {
#pragma unroll
            for (int r = 0; r < 4; r++) {
                int rr = arow + r * 32;
                int rv = rr < rows ? rr : rows - 1;
                aReg[r] = *reinterpret_cast<const float4*>(
                    g_act + (size_t)(base + row0 + rv) * F_FF + k1 + ac4 * 4);
            }
#pragma unroll
            for (int r = 0; r < 4; r++) {
                int kk = brow + r * 8;
                const int* wr = wrow_base + (size_t)(k1 + kk) * D_MODEL + n0;
                bReg[r] = *reinterpret_cast<const int4*>(wr + bc4 * 4);
            }
        }

        // ---- mma phase ----
#pragma unroll
        for (int ks = 0; ks < 4; ks++) {
            uint32_t b[4][2];
#pragma unroll
            for (int nf = 0; nf < 4; nf++) {
                int n = wn * 32 + nf * 8 + gid;
                b[nf][0] = __float_as_uint(Bs[ks * 8 + tig][n]);
                b[nf][1] = __float_as_uint(Bs[ks * 8 + tig + 4][n]);
            }
#pragma unroll
            for (int mf = 0; mf < 4; mf++) {
                int m = wm * 64 + mf * 16;
                uint32_t a[4];
                a[0] = __float_as_uint(As[m + gid][ks * 8 + tig]);
                a[1] = __float_as_uint(As[m + gid + 8][ks * 8 + tig]);
                a[2] = __float_as_uint(As[m + gid][ks * 8 + tig + 4]);
                a[3] = __float_as_uint(As[m + gid + 8][ks * 8 + tig + 4]);
#pragma unroll
                for (int nf = 0; nf < 4; nf++)
                    MMA_TF32(acc[mf][nf], a, b[nf]);
            }
        }
        __syncthreads();
    }
#pragma unroll
    for (int mf = 0; mf < 4; mf++) {
#pragma unroll
        for (int half = 0; half < 2; half++) {
            int ml = wm * 64 + mf * 16 + gid + half * 8;
            if (ml < rows) {
                size_t slot = (size_t)(base + row0 + ml);
#pragma unroll
                for (int nf = 0; nf < 4; nf++) {
                    int j = n0 + wn * 32 + nf * 8 + tig * 2;
                    *reinterpret_cast<float2*>(&g_y[slot * D_MODEL + j]) =
                        make_float2(acc[mf][nf][half * 2 + 0],
                                    acc[mf][nf][half * 2 + 1]);
                }
            }
        }
    }
}

// ---------------- combine: out[t] = c0*y[s0] + c1*y[s1] ----------------
__global__ void k_combine(float* __restrict__ out) {
    int t = blockIdx.x;
    int d = threadIdx.x * 4;
    int s0 = g_tok_slot[2 * t], s1 = g_tok_slot[2 * t + 1];
    float c0 = g_tok_coef[2 * t], c1 = g_tok_coef[2 * t + 1];
    float4 y0 = *reinterpret_cast<const float4*>(&g_y[(size_t)s0 * D_MODEL + d]);
    float4 y1 = *reinterpret_cast<const float4*>(&g_y[(size_t)s1 * D_MODEL + d]);
    float4 o;
    o.x = c0 * y0.x + c1 * y1.x;
    o.y = c0 * y0.y + c1 * y1.y;
    o.z = c0 * y0.z + c1 * y1.z;
    o.w = c0 * y0.w + c1 * y1.w;
    *reinterpret_cast<float4*>(out + (size_t)t * D_MODEL + d) = o;
}

// ---------------- launch ----------------
extern "C" void kernel_launch(void* const* d_in, const int* in_sizes, int n_in,
                              void* d_out, int out_size) {
    const float* x      = (const float*)d_in[0];
    const float* gating = (const float*)d_in[1];
    const int*   w1q    = (const int*)d_in[2];
    const int*   w2q    = (const int*)d_in[3];
    const float* w1s    = (const float*)d_in[4];
    const float* w2s    = (const float*)d_in[5];
    float* out = (float*)d_out;
    (void)in_sizes; (void)n_in; (void)out_size;

    k_zero_counts<<<1, 32>>>();
    k_route<<<T_TOKENS / 256, 256>>>(gating);
    k_place<<<1, 256>>>();

    dim3 g1(F_FF / 64, T_TOKENS / 128, E_EXPERTS);   // 64 x 32 x 8, early-exit on m
    k_gemm1<<<g1, 256>>>(x, w1q, w1s);

    dim3 g2(D_MODEL / 128, T_TOKENS / 128, E_EXPERTS);  // 8 x 32 x 8
    k_gemm2<<<g2, 256>>>(w2q, w2s);

    k_combine<<<T_TOKENS, 256>>>(out);
}

// round 7
// speedup vs baseline: 2.2639x; 1.7743x over previous
#include <cuda_runtime.h>
#include <cuda_fp16.h>
#include <cstdint>

#define E_EXPERTS 8
#define T_TOKENS  4096
#define D_MODEL   1024
#define F_FF      4096
#define TOPK      2
#define GROUPSZ   128

// ---------------- scratch ----------------
__device__ int    g_cnt[E_EXPERTS];
__device__ int    g_off[E_EXPERTS + 1];
__device__ int    g_tok[T_TOKENS * TOPK];
__device__ int    g_tok_eid[T_TOKENS * TOPK];
__device__ int    g_tok_slot[T_TOKENS * TOPK];
__device__ float  g_tok_coef[T_TOKENS * TOPK];
__device__ __half g_xh[(size_t)T_TOKENS * D_MODEL];            // x as fp16 (8 MB)
__device__ __half g_acth[(size_t)T_TOKENS * TOPK * F_FF];      // act fp16 (64 MB)
__device__ float  g_y[(size_t)T_TOKENS * TOPK * D_MODEL];      // 32 MB
// packed int4 codes, layout [e][kb][w][n]: nibble j of word = code k = kb*32 + w*8 + j
__device__ uint32_t g_pw1[(size_t)E_EXPERTS * 32 * 4 * (2 * F_FF)];   // 32 MB
__device__ uint32_t g_pw2[(size_t)E_EXPERTS * 128 * 4 * D_MODEL];     // 16 MB

// ---------------- helpers ----------------
#define MMA_F16(c, a, b)                                                       \
    asm volatile(                                                              \
        "mma.sync.aligned.m16n8k16.row.col.f32.f16.f16.f32 "                   \
        "{%0,%1,%2,%3}, {%4,%5,%6,%7}, {%8,%9}, {%0,%1,%2,%3};\n"              \
        : "+f"((c)[0]), "+f"((c)[1]), "+f"((c)[2]), "+f"((c)[3])               \
        : "r"((a)[0]), "r"((a)[1]), "r"((a)[2]), "r"((a)[3]),                  \
          "r"((b)[0]), "r"((b)[1]))

__device__ __forceinline__ uint32_t h2u(__half2 h) {
    return *reinterpret_cast<uint32_t*>(&h);
}
__device__ __forceinline__ uint32_t dq2(uint32_t v, int sh, float sc, float ns) {
    float f0 = fmaf((float)((v >> sh) & 15u), sc, ns);
    float f1 = fmaf((float)((v >> (sh + 4)) & 15u), sc, ns);
    return h2u(__floats2half2_rn(f0, f1));
}

// ---------------- routing ----------------
__global__ void k_zero_counts() {
    if (threadIdx.x < E_EXPERTS) g_cnt[threadIdx.x] = 0;
}

__global__ void k_route(const float* __restrict__ gating) {
    int t = blockIdx.x * blockDim.x + threadIdx.x;
    if (t >= T_TOKENS) return;
    float l[E_EXPERTS];
#pragma unroll
    for (int i = 0; i < E_EXPERTS; i++) l[i] = gating[t * E_EXPERTS + i];
    int ia = -1, ib = -1;
    float va = -1e30f, vb = -1e30f;
#pragma unroll
    for (int i = 0; i < E_EXPERTS; i++) {
        float v = l[i];
        if (v > va) { vb = va; ib = ia; va = v; ia = i; }
        else if (v > vb) { vb = v; ib = i; }
    }
    float eb = expf(vb - va);
    float inv = 1.0f / (1.0f + eb);
    g_tok_eid[2 * t + 0] = ia;
    g_tok_eid[2 * t + 1] = ib;
    g_tok_coef[2 * t + 0] = inv;
    g_tok_coef[2 * t + 1] = eb * inv;
    atomicAdd(&g_cnt[ia], 1);
    atomicAdd(&g_cnt[ib], 1);
}

__global__ void k_place() {
    int lane = threadIdx.x & 31;
    int e = threadIdx.x >> 5;
    if (e >= E_EXPERTS) return;
    int off = 0;
    for (int i = 0; i < e; i++) off += g_cnt[i];
    if (lane == 0) {
        g_off[e] = off;
        if (e == E_EXPERTS - 1) g_off[E_EXPERTS] = off + g_cnt[e];
    }
    int cursor = off;
    for (int base = 0; base < T_TOKENS; base += 32) {
        int t = base + lane;
        int e0 = g_tok_eid[2 * t], e1 = g_tok_eid[2 * t + 1];
        bool m0 = (e0 == e), m1 = (e1 == e);
        bool m = m0 || m1;
        unsigned mask = __ballot_sync(0xffffffffu, m);
        if (m) {
            int pos = cursor + __popc(mask & ((1u << lane) - 1u));
            g_tok[pos] = t;
            g_tok_slot[2 * t + (m0 ? 0 : 1)] = pos;
        }
        cursor += __popc(mask);
    }
}

// ---------------- prep: x -> fp16, int4 packing ----------------
__global__ void k_xh(const float* __restrict__ x) {
    size_t i = ((size_t)blockIdx.x * 256 + threadIdx.x) * 4;
    float4 v = *(const float4*)(x + i);
    uint2 o;
    o.x = h2u(__floats2half2_rn(v.x, v.y));
    o.y = h2u(__floats2half2_rn(v.z, v.w));
    *(uint2*)(&g_xh[i]) = o;
}

__global__ void k_pack1(const int* __restrict__ w1q) {
    uint32_t idx = blockIdx.x * 256 + threadIdx.x;   // e[3]|kb[5]|w[2]|n[13]
    uint32_t n = idx & 8191, w = (idx >> 13) & 3, kb = (idx >> 15) & 31, e = idx >> 20;
    const int* src = w1q + ((size_t)e * D_MODEL + kb * 32 + w * 8) * (2 * F_FF) + n;
    uint32_t acc = 0;
#pragma unroll
    for (int j = 0; j < 8; j++)
        acc |= ((uint32_t)src[(size_t)j * (2 * F_FF)] & 15u) << (4 * j);
    g_pw1[idx] = acc;
}
__global__ void k_pack2(const int* __restrict__ w2q) {
    uint32_t idx = blockIdx.x * 256 + threadIdx.x;   // e[3]|kb[7]|w[2]|n[10]
    uint32_t n = idx & 1023, w = (idx >> 10) & 3, kb = (idx >> 12) & 127, e = idx >> 19;
    const int* src = w2q + ((size_t)e * F_FF + kb * 32 + w * 8) * D_MODEL + n;
    uint32_t acc = 0;
#pragma unroll
    for (int j = 0; j < 8; j++)
        acc |= ((uint32_t)src[(size_t)j * D_MODEL] & 15u) << (4 * j);
    g_pw2[idx] = acc;
}

// ---------------- GEMM1: act = silu(x@Wg) * (x@Wu), fp16 mma ----------------
// Block 128m x (64 gate + 64 up), BK=64. 256 threads (8 warps, 2x4).
// Smem stride 72 halves => conflict-free STS.128 fills and LDS.32 frag loads.
__global__ __launch_bounds__(256, 2) void k_gemm1(const float* __restrict__ w1s)
{
    int e = blockIdx.z;
    int cnt = g_cnt[e];
    int row0 = blockIdx.y * 128;
    if (row0 >= cnt) return;
    int rows = min(cnt - row0, 128);
    int base = g_off[e];
    int n0 = blockIdx.x * 64;

    __shared__ __half As[128][72];
    __shared__ __half Bg[64][72];
    __shared__ __half Bu[64][72];
    __shared__ int toks[128];

    int tid = threadIdx.x;
    if (tid < 128) toks[tid] = g_tok[base + row0 + min(tid, rows - 1)];
    __syncthreads();

    int lane = tid & 31, wid = tid >> 5;
    int wm = wid >> 2, wn = wid & 3;        // warp: 64m x 16n per strip
    int gid = lane >> 2, tig = lane & 3;

    float accG[4][2][4], accU[4][2][4];
#pragma unroll
    for (int i = 0; i < 4; i++)
#pragma unroll
        for (int j = 0; j < 2; j++)
#pragma unroll
            for (int r = 0; r < 4; r++) { accG[i][j][r] = 0.f; accU[i][j][r] = 0.f; }

    // fill mapping
    int ar = tid >> 1, ah = tid & 1;                 // A: row, k-half (32 halves)
    int bst = tid >> 7, brr = (tid >> 1) & 63, bkh = tid & 1;  // B: strip, n-row, k-half
    size_t bcol = (size_t)bst * F_FF + n0 + brr;
    const __half* xrow = g_xh + (size_t)toks[ar] * D_MODEL + ah * 32;
    const uint32_t* pwbase = g_pw1 + (size_t)e * 32 * 4 * 8192 + bcol;
    const float* sbase = w1s + (size_t)e * 8 * (2 * F_FF) + bcol;

    uint4 aR[4];
    uint32_t bR[4];

    // prologue: stage k-tile 0
#pragma unroll
    for (int q = 0; q < 4; q++) aR[q] = *(const uint4*)(xrow + q * 8);
    {
        const uint32_t* pw = pwbase + (size_t)bkh * 4 * 8192;
#pragma unroll
        for (int w = 0; w < 4; w++) bR[w] = pw[(size_t)w * 8192];
    }

    for (int kt = 0; kt < D_MODEL / 64; kt++) {
        // ---- STS phase ----
        float sc = sbase[(size_t)(kt >> 1) * (2 * F_FF)];
        float ns = -8.0f * sc;
#pragma unroll
        for (int q = 0; q < 4; q++)
            *(uint4*)(&As[ar][ah * 32 + q * 8]) = aR[q];
        {
            __half(*B)[72] = bst ? Bu : Bg;
#pragma unroll
            for (int w = 0; w < 4; w++) {
                uint32_t v = bR[w];
                uint4 st;
                st.x = dq2(v, 0, sc, ns);
                st.y = dq2(v, 8, sc, ns);
                st.z = dq2(v, 16, sc, ns);
                st.w = dq2(v, 24, sc, ns);
                *(uint4*)(&B[brr][bkh * 32 + w * 8]) = st;
            }
        }
        __syncthreads();

        // ---- prefetch next k-tile ----
        if (kt + 1 < D_MODEL / 64) {
            const __half* xp = xrow + (kt + 1) * 64;
#pragma unroll
            for (int q = 0; q < 4; q++) aR[q] = *(const uint4*)(xp + q * 8);
            const uint32_t* pw = pwbase + ((size_t)(kt + 1) * 2 + bkh) * 4 * 8192;
#pragma unroll
            for (int w = 0; w < 4; w++) bR[w] = pw[(size_t)w * 8192];
        }

        // ---- mma phase: 4 k16 steps ----
#pragma unroll
        for (int ks = 0; ks < 4; ks++) {
            int kb2 = ks * 16 + 2 * tig;
            uint32_t bg[2][2], bu[2][2];
#pragma unroll
            for (int nf = 0; nf < 2; nf++) {
                int n = wn * 16 + nf * 8 + gid;
                bg[nf][0] = *(const uint32_t*)(&Bg[n][kb2]);
                bg[nf][1] = *(const uint32_t*)(&Bg[n][kb2 + 8]);
                bu[nf][0] = *(const uint32_t*)(&Bu[n][kb2]);
                bu[nf][1] = *(const uint32_t*)(&Bu[n][kb2 + 8]);
            }
#pragma unroll
            for (int mf = 0; mf < 4; mf++) {
                int m = wm * 64 + mf * 16;
                uint32_t a[4];
                a[0] = *(const uint32_t*)(&As[m + gid][kb2]);
                a[1] = *(const uint32_t*)(&As[m + gid + 8][kb2]);
                a[2] = *(const uint32_t*)(&As[m + gid][kb2 + 8]);
                a[3] = *(const uint32_t*)(&As[m + gid + 8][kb2 + 8]);
#pragma unroll
                for (int nf = 0; nf < 2; nf++) {
                    MMA_F16(accG[mf][nf], a, bg[nf]);
                    MMA_F16(accU[mf][nf], a, bu[nf]);
                }
            }
        }
        __syncthreads();
    }

    // epilogue: silu(gate)*up -> fp16 act
#pragma unroll
    for (int mf = 0; mf < 4; mf++) {
#pragma unroll
        for (int half_i = 0; half_i < 2; half_i++) {
            int ml = wm * 64 + mf * 16 + gid + half_i * 8;
            if (ml < rows) {
                __half* dst = g_acth + (size_t)(base + row0 + ml) * F_FF;
#pragma unroll
                for (int nf = 0; nf < 2; nf++) {
                    int j = n0 + wn * 16 + nf * 8 + tig * 2;
                    float gv0 = accG[mf][nf][half_i * 2 + 0];
                    float gv1 = accG[mf][nf][half_i * 2 + 1];
                    float uv0 = accU[mf][nf][half_i * 2 + 0];
                    float uv1 = accU[mf][nf][half_i * 2 + 1];
                    float v0 = gv0 / (1.0f + __expf(-gv0)) * uv0;
                    float v1 = gv1 / (1.0f + __expf(-gv1)) * uv1;
                    *(uint32_t*)(dst + j) = h2u(__floats2half2_rn(v0, v1));
                }
            }
        }
    }
}

// ---------------- GEMM2: y = act @ dequant(w2), fp16 mma ----------------
// Block 128m x 128n, BK=64. 256 threads (8 warps, 2x4), warp 64m x 32n.
__global__ __launch_bounds__(256, 2) void k_gemm2(const float* __restrict__ w2s)
{
    int e = blockIdx.z;
    int cnt = g_cnt[e];
    int row0 = blockIdx.y * 128;
    if (row0 >= cnt) return;
    int rows = min(cnt - row0, 128);
    int base = g_off[e];
    int n0 = blockIdx.x * 128;

    __shared__ __half As[128][72];
    __shared__ __half Bs[128][72];

    int tid = threadIdx.x;
    int lane = tid & 31, wid = tid >> 5;
    int wm = wid >> 2, wn = wid & 3;
    int gid = lane >> 2, tig = lane & 3;

    float acc[4][4][4];
#pragma unroll
    for (int i = 0; i < 4; i++)
#pragma unroll
        for (int j = 0; j < 4; j++)
#pragma unroll
            for (int r = 0; r < 4; r++) acc[i][j][r] = 0.f;

    int ar = tid >> 1, ah = tid & 1;
    int arv = min(ar, rows - 1);
    int brr = tid >> 1, bkh = tid & 1;
    const __half* arow = g_acth + (size_t)(base + row0 + arv) * F_FF + ah * 32;
    const uint32_t* pwbase = g_pw2 + (size_t)e * 128 * 4 * 1024 + n0 + brr;
    const float* sbase = w2s + (size_t)e * 32 * D_MODEL + n0 + brr;

    uint4 aR[4];
    uint32_t bR[4];

#pragma unroll
    for (int q = 0; q < 4; q++) aR[q] = *(const uint4*)(arow + q * 8);
    {
        const uint32_t* pw = pwbase + (size_t)bkh * 4 * 1024;
#pragma unroll
        for (int w = 0; w < 4; w++) bR[w] = pw[(size_t)w * 1024];
    }

    for (int kt = 0; kt < F_FF / 64; kt++) {
        // ---- STS phase ----
        float sc = sbase[(size_t)(kt >> 1) * D_MODEL];
        float ns = -8.0f * sc;
#pragma unroll
        for (int q = 0; q < 4; q++)
            *(uint4*)(&As[ar][ah * 32 + q * 8]) = aR[q];
#pragma unroll
        for (int w = 0; w < 4; w++) {
            uint32_t v = bR[w];
            uint4 st;
            st.x = dq2(v, 0, sc, ns);
            st.y = dq2(v, 8, sc, ns);
            st.z = dq2(v, 16, sc, ns);
            st.w = dq2(v, 24, sc, ns);
            *(uint4*)(&Bs[brr][bkh * 32 + w * 8]) = st;
        }
        __syncthreads();

        // ---- prefetch next k-tile ----
        if (kt + 1 < F_FF / 64) {
            const __half* ap = arow + (kt + 1) * 64;
#pragma unroll
            for (int q = 0; q < 4; q++) aR[q] = *(const uint4*)(ap + q * 8);
            const uint32_t* pw = pwbase + ((size_t)(kt + 1) * 2 + bkh) * 4 * 1024;
#pragma unroll
            for (int w = 0; w < 4; w++) bR[w] = pw[(size_t)w * 1024];
        }

        // ---- mma phase ----
#pragma unroll
        for (int ks = 0; ks < 4; ks++) {
            int kb2 = ks * 16 + 2 * tig;
            uint32_t b[4][2];
#pragma unroll
            for (int nf = 0; nf < 4; nf++) {
                int n = wn * 32 + nf * 8 + gid;
                b[nf][0] = *(const uint32_t*)(&Bs[n][kb2]);
                b[nf][1] = *(const uint32_t*)(&Bs[n][kb2 + 8]);
            }
#pragma unroll
            for (int mf = 0; mf < 4; mf++) {
                int m = wm * 64 + mf * 16;
                uint32_t a[4];
                a[0] = *(const uint32_t*)(&As[m + gid][kb2]);
                a[1] = *(const uint32_t*)(&As[m + gid + 8][kb2]);
                a[2] = *(const uint32_t*)(&As[m + gid][kb2 + 8]);
                a[3] = *(const uint32_t*)(&As[m + gid + 8][kb2 + 8]);
#pragma unroll
                for (int nf = 0; nf < 4; nf++)
                    MMA_F16(acc[mf][nf], a, b[nf]);
            }
        }
        __syncthreads();
    }

#pragma unroll
    for (int mf = 0; mf < 4; mf++) {
#pragma unroll
        for (int half_i = 0; half_i < 2; half_i++) {
            int ml = wm * 64 + mf * 16 + gid + half_i * 8;
            if (ml < rows) {
                float* dst = g_y + (size_t)(base + row0 + ml) * D_MODEL;
#pragma unroll
                for (int nf = 0; nf < 4; nf++) {
                    int j = n0 + wn * 32 + nf * 8 + tig * 2;
                    *(float2*)(dst + j) =
                        make_float2(acc[mf][nf][half_i * 2 + 0],
                                    acc[mf][nf][half_i * 2 + 1]);
                }
            }
        }
    }
}

// ---------------- combine ----------------
__global__ void k_combine(float* __restrict__ out) {
    int t = blockIdx.x;
    int d = threadIdx.x * 4;
    int s0 = g_tok_slot[2 * t], s1 = g_tok_slot[2 * t + 1];
    float c0 = g_tok_coef[2 * t], c1 = g_tok_coef[2 * t + 1];
    float4 y0 = *(const float4*)(&g_y[(size_t)s0 * D_MODEL + d]);
    float4 y1 = *(const float4*)(&g_y[(size_t)s1 * D_MODEL + d]);
    float4 o;
    o.x = c0 * y0.x + c1 * y1.x;
    o.y = c0 * y0.y + c1 * y1.y;
    o.z = c0 * y0.z + c1 * y1.z;
    o.w = c0 * y0.w + c1 * y1.w;
    *(float4*)(out + (size_t)t * D_MODEL + d) = o;
}

// ---------------- launch ----------------
extern "C" void kernel_launch(void* const* d_in, const int* in_sizes, int n_in,
                              void* d_out, int out_size) {
    const float* x      = (const float*)d_in[0];
    const float* gating = (const float*)d_in[1];
    const int*   w1q    = (const int*)d_in[2];
    const int*   w2q    = (const int*)d_in[3];
    const float* w1s    = (const float*)d_in[4];
    const float* w2s    = (const float*)d_in[5];
    float* out = (float*)d_out;
    (void)in_sizes; (void)n_in; (void)out_size;

    k_xh<<<(T_TOKENS * D_MODEL) / (256 * 4), 256>>>(x);
    k_pack1<<<(8u * 32 * 4 * 8192) / 256, 256>>>(w1q);
    k_pack2<<<(8u * 128 * 4 * 1024) / 256, 256>>>(w2q);
    k_zero_counts<<<1, 32>>>();
    k_route<<<T_TOKENS / 256, 256>>>(gating);
    k_place<<<1, 256>>>();

    dim3 g1(F_FF / 64, T_TOKENS / 128, E_EXPERTS);     // 64 x 32 x 8
    k_gemm1<<<g1, 256>>>(w1s);

    dim3 g2(D_MODEL / 128, T_TOKENS / 128, E_EXPERTS); // 8 x 32 x 8
    k_gemm2<<<g2, 256>>>(w2s);

    k_combine<<<T_TOKENS, 256>>>(out);
}